// round 5
// baseline (speedup 1.0000x reference)
#include <cuda_runtime.h>
#include <math_constants.h>

#define NB 4
#define NN 16384
#define NM 512
#define NC 128
#define NK 16
#define NL 6
#define NSTEPS 5
#define GG 32
#define G3 (GG*GG*GG)

// ---------------- scratch (device globals: no allocations allowed) ----------
__device__ float g_feats[NB*NN*NC];            // encoder output
__device__ float g_Qf[NB*NN*NC];               // feats @ beta^T + b
__device__ float g_Gf[NB*NN*NC];               // feats @ gamma^T + b
__device__ float g_pos4[NB*NN*4];              // padded positions (x,y,z,0)
__device__ float g_wsel[NB*NM*NL*NC];          // selector walks
__device__ float g_rout[2][NB*NM*NL*NC];       // routed walks ping-pong
__device__ float g_disp[NB*NM*3];              // per-step displacements
// spatial grid (rebuilt every step)
__device__ unsigned g_bboxi[NB][6];            // encoded minx,miny,minz,maxx,maxy,maxz
__device__ int      g_cellcnt[NB][G3];         // histogram, then fill cursor
__device__ int      g_cellstart[NB][G3+1];
__device__ float4   g_spos[NB*NN];             // cell-sorted positions, .w = idx bits

// ---------------- order-preserving float<->uint encoding --------------------
__device__ __forceinline__ unsigned encf(float f) {
    int i = __float_as_int(f);
    return (i >= 0) ? ((unsigned)i | 0x80000000u) : ~(unsigned)i;
}
__device__ __forceinline__ float decf(unsigned k) {
    return __int_as_float((k & 0x80000000u) ? (int)(k ^ 0x80000000u) : (int)~k);
}

struct BBox { float mnx, mny, mnz, ivx, ivy, ivz, hmin; };
__device__ __forceinline__ BBox load_bbox(int b) {
    BBox bb;
    bb.mnx = decf(g_bboxi[b][0]); bb.mny = decf(g_bboxi[b][1]); bb.mnz = decf(g_bboxi[b][2]);
    float rx = fmaxf(decf(g_bboxi[b][3]) - bb.mnx, 1e-6f);
    float ry = fmaxf(decf(g_bboxi[b][4]) - bb.mny, 1e-6f);
    float rz = fmaxf(decf(g_bboxi[b][5]) - bb.mnz, 1e-6f);
    bb.ivx = (float)GG / rx; bb.ivy = (float)GG / ry; bb.ivz = (float)GG / rz;
    bb.hmin = fminf(rx, fminf(ry, rz)) * (1.0f / GG);
    return bb;
}
__device__ __forceinline__ int clampg(int v) { return min(GG-1, max(0, v)); }
__device__ __forceinline__ int cell_of(const BBox& bb, float x, float y, float z,
                                       int& cx, int& cy, int& cz) {
    cx = clampg((int)((x - bb.mnx) * bb.ivx));
    cy = clampg((int)((y - bb.mny) * bb.ivy));
    cz = clampg((int)((z - bb.mnz) * bb.ivz));
    return (cz*GG + cy)*GG + cx;
}

__device__ __forceinline__ void bbox_reset(int gid) {
    if (gid < NB*6) ((unsigned*)g_bboxi)[gid] = (gid % 6) < 3 ? 0xFFFFFFFFu : 0u;
}

// ---------------- init: padded positions from xyz (+ bbox reset) ------------
__global__ void init_pos_kernel(const float* __restrict__ xyz) {
    int i = blockIdx.x * blockDim.x + threadIdx.x;
    bbox_reset(i);
    if (i < NB*NN) {
        float x = xyz[i*3+0], y = xyz[i*3+1], z = xyz[i*3+2];
        float4 v = make_float4(x, y, z, 0.f);
        *(float4*)&g_pos4[(size_t)i*4] = v;
    }
}

// ---------------- grid prep: zero histogram + bbox atomic reduce ------------
// 256 blocks x 256 threads. All threads zero counters; 64 blocks/batch reduce
// bbox (1 point per thread) via smem + per-block atomics on encoded uints.
__global__ void gridprep_kernel() {
    __shared__ unsigned smn[3][8], smx[3][8];
    int tid = threadIdx.x;
    int gid = blockIdx.x * 256 + tid;
    // zero histogram: NB*G3 = 131072 ints over 65536 threads
    ((int*)g_cellcnt)[gid] = 0;
    ((int*)g_cellcnt)[gid + 65536] = 0;
    // bbox reduce
    int b = blockIdx.x >> 6;
    int i = (blockIdx.x & 63) * 256 + tid;
    const float4 p = *(const float4*)&g_pos4[((size_t)b*NN + i) * 4];
    unsigned ex = encf(p.x), ey = encf(p.y), ez = encf(p.z);
    unsigned nx = ex, ny = ey, nz = ez;
    #pragma unroll
    for (int off = 16; off; off >>= 1) {
        nx = min(nx, __shfl_xor_sync(0xffffffffu, nx, off));
        ny = min(ny, __shfl_xor_sync(0xffffffffu, ny, off));
        nz = min(nz, __shfl_xor_sync(0xffffffffu, nz, off));
        ex = max(ex, __shfl_xor_sync(0xffffffffu, ex, off));
        ey = max(ey, __shfl_xor_sync(0xffffffffu, ey, off));
        ez = max(ez, __shfl_xor_sync(0xffffffffu, ez, off));
    }
    int warp = tid >> 5;
    if ((tid & 31) == 0) {
        smn[0][warp] = nx; smn[1][warp] = ny; smn[2][warp] = nz;
        smx[0][warp] = ex; smx[1][warp] = ey; smx[2][warp] = ez;
    }
    __syncthreads();
    if (tid < 3) {
        unsigned mn = 0xFFFFFFFFu, mx = 0u;
        #pragma unroll
        for (int w = 0; w < 8; w++) { mn = min(mn, smn[tid][w]); mx = max(mx, smx[tid][w]); }
        atomicMin(&g_bboxi[b][tid], mn);
        atomicMax(&g_bboxi[b][tid + 3], mx);
    }
}

// ---------------- histogram ----------------------------------------------
__global__ void hist_kernel() {
    int gid = blockIdx.x * 256 + threadIdx.x;   // 65536 = NB*NN
    int b = gid >> 14, i = gid & (NN-1);
    BBox bb = load_bbox(b);
    const float4 p = *(const float4*)&g_pos4[((size_t)b*NN + i) * 4];
    int cx, cy, cz;
    int c = cell_of(bb, p.x, p.y, p.z, cx, cy, cz);
    atomicAdd(&g_cellcnt[b][c], 1);
}

// ---------------- exclusive scan over 32768 cells (1 block / batch) --------
__global__ void scan_kernel() {
    __shared__ int ss[1024];
    int b = blockIdx.x, t = threadIdx.x;
    int base = t * (G3/1024);                  // 32 cells / thread
    int s = 0;
    #pragma unroll
    for (int k = 0; k < G3/1024; k++) s += g_cellcnt[b][base + k];
    int mysum = s;
    ss[t] = s; __syncthreads();
    for (int off = 1; off < 1024; off <<= 1) {
        int v = (t >= off) ? ss[t - off] : 0;
        __syncthreads();
        ss[t] += v;
        __syncthreads();
    }
    int running = ss[t] - mysum;               // exclusive prefix
    #pragma unroll
    for (int k = 0; k < G3/1024; k++) {
        int c = base + k;
        int v = g_cellcnt[b][c];
        g_cellstart[b][c] = running;
        g_cellcnt[b][c]  = running;            // fill cursor
        running += v;
    }
    if (t == 0) g_cellstart[b][G3] = NN;
}

// ---------------- scatter points into cell-sorted order --------------------
__global__ void scatterpts_kernel() {
    int gid = blockIdx.x * 256 + threadIdx.x;
    int b = gid >> 14, i = gid & (NN-1);
    BBox bb = load_bbox(b);
    const float4 p = *(const float4*)&g_pos4[((size_t)b*NN + i) * 4];
    int cx, cy, cz;
    int c = cell_of(bb, p.x, p.y, p.z, cx, cy, cz);
    int slot = atomicAdd(&g_cellcnt[b][c], 1);
    g_spos[(size_t)b*NN + slot] = make_float4(p.x, p.y, p.z, __int_as_float(i));
}

// ---------------- encoder: feats = relu(xyz@W1^T+b1)@W2^T+b2 ---------------
__global__ void encode_kernel(const float* __restrict__ xyz,
                              const float* __restrict__ w1, const float* __restrict__ b1,
                              const float* __restrict__ w2, const float* __restrict__ b2) {
    __shared__ float h[4][64];
    int tid = threadIdx.x;              // 128 threads
    int p0 = blockIdx.x * 4;            // 4 points / block
    for (int i = tid; i < 4*64; i += 128) {
        int pt = i >> 6, j = i & 63;
        const float* x = xyz + (size_t)(p0 + pt) * 3;
        float v = b1[j] + w1[j*3+0]*x[0] + w1[j*3+1]*x[1] + w1[j*3+2]*x[2];
        h[pt][j] = fmaxf(v, 0.f);
    }
    __syncthreads();
    float acc[4];
    #pragma unroll
    for (int p = 0; p < 4; p++) acc[p] = b2[tid];
    const float4* wr = (const float4*)(w2 + (size_t)tid * 64);
    #pragma unroll
    for (int j4 = 0; j4 < 16; j4++) {
        float4 w = wr[j4];
        #pragma unroll
        for (int p = 0; p < 4; p++) {
            float4 hv = *(const float4*)&h[p][4*j4];
            acc[p] += w.x*hv.x + w.y*hv.y + w.z*hv.z + w.w*hv.w;
        }
    }
    #pragma unroll
    for (int p = 0; p < 4; p++)
        g_feats[(size_t)(p0 + p) * NC + tid] = acc[p];
}

// ---------------- beta/gamma projections (precomputed once) ----------------
__global__ void proj_kernel(const float* __restrict__ bw, const float* __restrict__ bb,
                            const float* __restrict__ gw, const float* __restrict__ gb) {
    __shared__ float sf[16][128];
    int c = threadIdx.x;                       // 128 threads
    size_t base = (size_t)blockIdx.x * 16 * 128;
    for (int i = c; i < 16*128; i += 128) sf[i>>7][i&127] = g_feats[base + i];
    __syncthreads();
    float accQ[16], accG[16];
    float biasQ = bb[c], biasG = gb[c];
    #pragma unroll
    for (int p = 0; p < 16; p++) { accQ[p] = biasQ; accG[p] = biasG; }
    const float4* wq = (const float4*)(bw + (size_t)c * 128);
    const float4* wg = (const float4*)(gw + (size_t)c * 128);
    for (int j4 = 0; j4 < 32; j4++) {
        float4 a = wq[j4];
        float4 g = wg[j4];
        #pragma unroll
        for (int p = 0; p < 16; p++) {
            float4 f = *(const float4*)&sf[p][4*j4];
            accQ[p] += a.x*f.x + a.y*f.y + a.z*f.z + a.w*f.w;
            accG[p] += g.x*f.x + g.y*f.y + g.z*f.z + g.w*f.w;
        }
    }
    #pragma unroll
    for (int p = 0; p < 16; p++) {
        g_Qf[base + (size_t)p*128 + c] = accQ[p];
        g_Gf[base + (size_t)p*128 + c] = accG[p];
    }
}

// ---------------- fused per-step selector with grid-accelerated KNN --------
// 512 blocks x 128 threads, 1 query per warp, all NL-1 levels internal.
// Expanding-ring search over the cell grid; warp-distributed sorted top-17
// (lanes 0..16). Exact: terminate ring r when tau <= ((r-1)*hmin)^2.
#define KWARPS 4
#define KTPB 128

__device__ __forceinline__ void knn_scan_range(const float4* __restrict__ sp,
                                               int s, int e,
                                               float qx, float qy, float qz,
                                               float& ld, int& li, float& tau,
                                               int lane) {
    for (int base = s; base < e; base += 32) {
        int j = base + lane;
        float d = CUDART_INF_F;
        int ci = 0x7FFFFFFF;
        if (j < e) {
            float4 p = sp[j];
            float dx = p.x - qx, dy = p.y - qy, dz = p.z - qz;
            d = fmaf(dz, dz, fmaf(dy, dy, dx*dx));
            ci = __float_as_int(p.w);
        }
        unsigned bal = __ballot_sync(0xffffffffu, d < tau);
        if (bal) {
            do {
                int src2 = __ffs(bal) - 1; bal &= bal - 1;
                float dc = __shfl_sync(0xffffffffu, d, src2);
                int   ic = __shfl_sync(0xffffffffu, ci, src2);
                float pd = __shfl_up_sync(0xffffffffu, ld, 1);
                int   pi = __shfl_up_sync(0xffffffffu, li, 1);
                unsigned lt = __ballot_sync(0xffffffffu,
                        (ld < dc) || ((ld == dc) && (li < ic))) & 0x1FFFFu;
                int pn = __popc(lt);
                if (lane < 17) {
                    if (lane == pn)      { ld = dc; li = ic; }
                    else if (lane > pn)  { ld = pd; li = pi; }
                }
            } while (bal);
            tau = __shfl_sync(0xffffffffu, ld, 16);
        }
    }
}

__global__ __launch_bounds__(KTPB, 8)
void knn_step_kernel(const int* __restrict__ start,
                     const float* __restrict__ gumbel, int t) {
    __shared__ int sknn[KWARPS][NK];
    const int bpb = NM / KWARPS;               // 128 blocks per batch
    int b  = blockIdx.x / bpb;
    int warp = threadIdx.x >> 5, lane = threadIdx.x & 31;
    int m = (blockIdx.x % bpb) * KWARPS + warp;
    int gw = b*NM + m;
    int qidx = start[gw];
    const float4* pos = (const float4*)(g_pos4 + (size_t)b * NN * 4);
    const float4* sp  = g_spos + (size_t)b * NN;
    const int* cs = g_cellstart[b];
    const float* G = g_Gf + (size_t)b*NN*NC;
    BBox bb = load_bbox(b);

    // walk[0] = feats[start]
    {
        const float* fr = g_feats + ((size_t)b*NN + qidx) * NC;
        float* wr = g_wsel + (size_t)gw * NL * NC;
        #pragma unroll
        for (int r = 0; r < 4; r++) wr[lane + 32*r] = fr[lane + 32*r];
    }

    for (int l = 0; l < NL-1; l++) {
        float4 qp = pos[qidx];
        float qx = qp.x, qy = qp.y, qz = qp.z;
        int cx, cy, cz;
        cell_of(bb, qx, qy, qz, cx, cy, cz);
        float ld = CUDART_INF_F;
        int   li = 0x7FFFFFFF;
        float tau = CUDART_INF_F;

        for (int r = 0; r <= 2*GG; r++) {
            if (r > 0) {
                float bound = (float)(r - 1) * bb.hmin;
                if (tau <= bound * bound) break;
            }
            for (int dz = -r; dz <= r; dz++) {
                int z = cz + dz;
                if ((unsigned)z >= GG) continue;
                int az = dz < 0 ? -dz : dz;
                for (int dy = -r; dy <= r; dy++) {
                    int y = cy + dy;
                    if ((unsigned)y >= GG) continue;
                    int ay = dy < 0 ? -dy : dy;
                    int rowb = (z*GG + y)*GG;
                    if (az == r || ay == r) {
                        int xlo = max(cx - r, 0), xhi = min(cx + r, GG-1);
                        knn_scan_range(sp, cs[rowb+xlo], cs[rowb+xhi+1],
                                       qx, qy, qz, ld, li, tau, lane);
                    } else {
                        int xl = cx - r;
                        if (xl >= 0)
                            knn_scan_range(sp, cs[rowb+xl], cs[rowb+xl+1],
                                           qx, qy, qz, ld, li, tau, lane);
                        int xh = cx + r;
                        if (xh < GG)
                            knn_scan_range(sp, cs[rowb+xh], cs[rowb+xh+1],
                                           qx, qy, qz, ld, li, tau, lane);
                    }
                }
            }
        }
        // lane 0 = self. neighbors = lanes 1..16 ascending (d, idx).
        if (lane >= 1 && lane < 17) sknn[warp][lane - 1] = li;
        __syncwarp();

        // logits + gumbel argmax
        const float* Q = g_Qf + ((size_t)b*NN + qidx) * NC;
        float qv0 = Q[lane], qv1 = Q[lane+32], qv2 = Q[lane+64], qv3 = Q[lane+96];
        float pk[16];
        #pragma unroll
        for (int k = 0; k < 16; k++) {
            const float* gr = G + (size_t)sknn[warp][k] * NC;
            pk[k] = qv0*gr[lane] + qv1*gr[lane+32] + qv2*gr[lane+64] + qv3*gr[lane+96];
        }
        #pragma unroll
        for (int k = 0; k < 16; k++) {
            #pragma unroll
            for (int off = 16; off; off >>= 1)
                pk[k] += __shfl_xor_sync(0xffffffffu, pk[k], off);
        }
        const float* gm = gumbel + ((((size_t)t*(NL-1) + l)*NB + b)*NM + m) * NK;
        float best = -CUDART_INF_F; int bk = 0;
        #pragma unroll
        for (int k = 0; k < 16; k++) {
            float s = pk[k] / 11.313708498984761f + gm[k];   // /sqrt(128)
            if (s > best) { best = s; bk = k; }
        }
        qidx = sknn[warp][bk];
        const float* fr = g_feats + ((size_t)b*NN + qidx) * NC;
        float* wr = g_wsel + ((size_t)gw * NL + (l + 1)) * NC;
        #pragma unroll
        for (int r = 0; r < 4; r++) wr[lane + 32*r] = fr[lane + 32*r];
    }
}

// ---------------- f32x2 packed helpers --------------------------------------
__device__ __forceinline__ void dfma2(unsigned long long& d,
                                      unsigned long long a,
                                      unsigned long long b) {
    asm("fma.rn.f32x2 %0, %1, %2, %0;" : "+l"(d) : "l"(a), "l"(b));
}
__device__ __forceinline__ unsigned long long packdup(float w) {
    unsigned long long r;
    asm("mov.b64 %0, {%1, %1};" : "=l"(r) : "f"(w));
    return r;
}
__device__ __forceinline__ void unpack2(unsigned long long a, float& lo, float& hi) {
    asm("mov.b64 {%0, %1}, %2;" : "=f"(lo), "=f"(hi) : "l"(a));
}

// ---------------- route + predict fused ------------------------------------
__device__ __forceinline__ void mm128i(const float (*in)[128][2],
                                       const float* __restrict__ W,
                                       const float* __restrict__ bias,
                                       float (*out)[128][2],
                                       int tid, bool doRelu) {
    unsigned long long acc[6];
    unsigned long long bb = packdup(bias[tid]);
    #pragma unroll
    for (int i = 0; i < 6; i++) acc[i] = bb;
    const float4* wr = (const float4*)(W + (size_t)tid * 128);
    const unsigned long long* inu = (const unsigned long long*)in;
    for (int j4 = 0; j4 < 32; j4++) {
        float4 w = __ldg(&wr[j4]);
        unsigned long long w0 = packdup(w.x), w1 = packdup(w.y);
        unsigned long long w2 = packdup(w.z), w3 = packdup(w.w);
        #pragma unroll
        for (int l2 = 0; l2 < 6; l2++) {
            const unsigned long long* row = inu + l2*128 + 4*j4;
            dfma2(acc[l2], row[0], w0);
            dfma2(acc[l2], row[1], w1);
            dfma2(acc[l2], row[2], w2);
            dfma2(acc[l2], row[3], w3);
        }
    }
    #pragma unroll
    for (int l2 = 0; l2 < 6; l2++) {
        float v0, v1;
        unpack2(acc[l2], v0, v1);
        if (doRelu) { v0 = fmaxf(v0, 0.f); v1 = fmaxf(v1, 0.f); }
        out[l2][tid][0] = v0;
        out[l2][tid][1] = v1;
    }
}

__global__ void route_kernel(const float* __restrict__ w_in, const float* __restrict__ b_in,
                             const float* __restrict__ w_out, const float* __restrict__ b_out,
                             const float* __restrict__ rt_w1, const float* __restrict__ rt_b1,
                             const float* __restrict__ rt_w2, const float* __restrict__ rt_b2,
                             const float* __restrict__ pw1, const float* __restrict__ pb1,
                             const float* __restrict__ pw2, const float* __restrict__ pb2,
                             int curBuf, int prevBuf) {
    __shared__ __align__(16) float xin[6][128][2];
    __shared__ __align__(16) float pin[6][128][2];
    __shared__ __align__(16) float qs[6][128][2];
    __shared__ __align__(16) float ks[6][128][2];
    __shared__ __align__(16) float vs[6][128][2];
    __shared__ float sc[2][4][6][6];
    int tid = threadIdx.x;
    size_t seq0 = (size_t)blockIdx.x * 2;
    const float* curr = g_wsel;
    const float* prev = (prevBuf < 0) ? g_wsel : g_rout[prevBuf];
    for (int i = tid; i < 2*6*128; i += 128) {
        int s = i / 768, r = i % 768;
        ((float*)xin)[r*2 + s] = curr[(seq0 + s)*768 + r];
        ((float*)pin)[r*2 + s] = prev[(seq0 + s)*768 + r];
    }
    __syncthreads();
    mm128i(xin, w_in,            b_in,        qs, tid, false);
    mm128i(pin, w_in + 128*128,  b_in + 128,  ks, tid, false);
    mm128i(pin, w_in + 256*128,  b_in + 256,  vs, tid, false);
    __syncthreads();
    int warp = tid >> 5, lane = tid & 31;
    for (int pp = warp; pp < 8; pp += 4) {
        int s = pp >> 2, h = pp & 3;
        for (int e = lane; e < 36; e += 32) {
            int lq = e / 6, lk = e % 6;
            float d = 0.f;
            #pragma unroll
            for (int dd = 0; dd < 32; dd++)
                d += qs[lq][h*32 + dd][s] * ks[lk][h*32 + dd][s];
            sc[s][h][lq][lk] = d / 5.656854249492381f;
        }
        __syncwarp();
        if (lane < 6) {
            float mx = -CUDART_INF_F;
            #pragma unroll
            for (int j = 0; j < 6; j++) mx = fmaxf(mx, sc[s][h][lane][j]);
            float ex[6]; float sum = 0.f;
            #pragma unroll
            for (int j = 0; j < 6; j++) { ex[j] = expf(sc[s][h][lane][j] - mx); sum += ex[j]; }
            #pragma unroll
            for (int j = 0; j < 6; j++) sc[s][h][lane][j] = ex[j] / sum;
        }
        __syncwarp();
        for (int lq = 0; lq < 6; lq++) {
            float o = 0.f;
            #pragma unroll
            for (int j = 0; j < 6; j++) o += sc[s][h][lq][j] * vs[j][h*32 + lane][s];
            xin[lq][h*32 + lane][s] = o;
        }
    }
    __syncthreads();
    mm128i(xin, w_out, b_out, pin, tid, false);
    __syncthreads();
    mm128i(pin, rt_w1, rt_b1, qs, tid, true);
    __syncthreads();
    mm128i(qs, rt_w2, rt_b2, ks, tid, false);
    __syncthreads();
    float* dst = g_rout[curBuf] + seq0*768;
    for (int i = tid; i < 2*6*128; i += 128) {
        int s = i / 768, r = i % 768;
        dst[(size_t)s*768 + r] = ((float*)ks)[r*2 + s];
    }
    // ---- fused predict head for the block's 2 sequences ----
    float* xv = (float*)qs;    // x: [2][256]
    float* hv = (float*)vs;    // h: [2][64]
    {
        int c = tid;
        #pragma unroll
        for (int s = 0; s < 2; s++) {
            float cent = ks[0][c][s];
            float sum = 0.f;
            #pragma unroll
            for (int l2 = 1; l2 < 6; l2++) sum += (ks[l2][c][s] - cent);
            xv[s*256 + c]       = sum * (1.0f / 5.0f);
            xv[s*256 + 128 + c] = cent;
        }
    }
    __syncthreads();
    {
        int s = tid >> 6, j = tid & 63;
        float acc = pb1[j];
        const float4* wr = (const float4*)(pw1 + (size_t)j * 256);
        const float4* xr = (const float4*)(xv + s*256);
        #pragma unroll 8
        for (int j4 = 0; j4 < 64; j4++) {
            float4 wv = wr[j4];
            float4 x4 = xr[j4];
            acc += wv.x*x4.x + wv.y*x4.y + wv.z*x4.z + wv.w*x4.w;
        }
        hv[s*64 + j] = fmaxf(acc, 0.f);
    }
    __syncthreads();
    if (tid < 6) {
        int s = tid / 3, o = tid % 3;
        float acc = pb2[o];
        const float* wr = pw2 + o * 64;
        const float* hh = hv + s*64;
        #pragma unroll 8
        for (int j = 0; j < 64; j++) acc += wr[j] * hh[j];
        g_disp[(seq0 + s)*3 + o] = tanhf(acc);
    }
}

// ---------------- deterministic duplicate-aware scatter-add (+bbox reset) ---
__global__ void scatter_kernel(const int* __restrict__ start) {
    int gid = blockIdx.x * blockDim.x + threadIdx.x;
    bbox_reset(gid);
    if (gid >= NB*NM) return;
    int b = gid >> 9, m = gid & 511;
    int n = start[gid];
    const int* sb = start + b * NM;
    for (int j = 0; j < m; j++) if (sb[j] == n) return;
    float sx = 0.f, sy = 0.f, sz = 0.f;
    for (int j = m; j < NM; j++) {
        if (sb[j] == n) {
            const float* d = g_disp + (size_t)(b*NM + j) * 3;
            sx += d[0]; sy += d[1]; sz += d[2];
        }
    }
    float* p = g_pos4 + ((size_t)b*NN + n) * 4;
    p[0] += sx; p[1] += sy; p[2] += sz;
}

// ---------------- finalize: padded positions -> output ---------------------
__global__ void finalize_kernel(float* __restrict__ out) {
    int i = blockIdx.x * blockDim.x + threadIdx.x;
    if (i < NB*NN) {
        out[i*3+0] = g_pos4[(size_t)i*4+0];
        out[i*3+1] = g_pos4[(size_t)i*4+1];
        out[i*3+2] = g_pos4[(size_t)i*4+2];
    }
}

// ---------------- host driver ----------------------------------------------
extern "C" void kernel_launch(void* const* d_in, const int* in_sizes, int n_in,
                              void* d_out, int out_size) {
    (void)in_sizes; (void)n_in; (void)out_size;
    const float* xyz      = (const float*)d_in[0];
    const int*   start    = (const int*)  d_in[1];
    const float* gumbel   = (const float*)d_in[2];
    const float* enc_w1   = (const float*)d_in[3];
    const float* enc_b1   = (const float*)d_in[4];
    const float* enc_w2   = (const float*)d_in[5];
    const float* enc_b2   = (const float*)d_in[6];
    const float* beta_w   = (const float*)d_in[7];
    const float* beta_b   = (const float*)d_in[8];
    const float* gamma_w  = (const float*)d_in[9];
    const float* gamma_b  = (const float*)d_in[10];
    const float* attn_w_in  = (const float*)d_in[11];
    const float* attn_b_in  = (const float*)d_in[12];
    const float* attn_w_out = (const float*)d_in[13];
    const float* attn_b_out = (const float*)d_in[14];
    const float* rt_w1    = (const float*)d_in[15];
    const float* rt_b1    = (const float*)d_in[16];
    const float* rt_w2    = (const float*)d_in[17];
    const float* rt_b2    = (const float*)d_in[18];
    const float* pred_w1  = (const float*)d_in[19];
    const float* pred_b1  = (const float*)d_in[20];
    const float* pred_w2  = (const float*)d_in[21];
    const float* pred_b2  = (const float*)d_in[22];

    init_pos_kernel<<<(NB*NN + 127)/128, 128>>>(xyz);
    encode_kernel<<<NB*NN/4, 128>>>(xyz, enc_w1, enc_b1, enc_w2, enc_b2);
    proj_kernel<<<NB*NN/16, 128>>>(beta_w, beta_b, gamma_w, gamma_b);

    for (int t = 0; t < NSTEPS; t++) {
        int cur = t & 1;
        int prv = (t == 0) ? -1 : (1 - cur);
        gridprep_kernel<<<256, 256>>>();
        hist_kernel<<<256, 256>>>();
        scan_kernel<<<NB, 1024>>>();
        scatterpts_kernel<<<256, 256>>>();
        knn_step_kernel<<<NB*NM/KWARPS, KTPB>>>(start, gumbel, t);
        route_kernel<<<NB*NM/2, 128>>>(attn_w_in, attn_b_in, attn_w_out, attn_b_out,
                                       rt_w1, rt_b1, rt_w2, rt_b2,
                                       pred_w1, pred_b1, pred_w2, pred_b2, cur, prv);
        scatter_kernel<<<(NB*NM + 127)/128, 128>>>(start);
    }
    finalize_kernel<<<(NB*NN + 127)/128, 128>>>((float*)d_out);
}